// round 1
// baseline (speedup 1.0000x reference)
#include <cuda_runtime.h>
#include <cstdint>

#define BATCH   64
#define SEQ     2048
#define DM      128
#define G3      384
#define XSTRIDE 2052
#define NWIN    64
#define WLEN    64
#define PRED    4
#define WG      4

// ---------------- persistent device scratch (no allocs allowed) ----------------
__device__ float g_x[BATCH * XSTRIDE];          // sequence extended with predictions
__device__ float g_H[BATCH * DM];               // global GRU state
__device__ float g_S[BATCH * NWIN * DM];        // window GRU final states (current step)
__device__ int   g_starts[BATCH * NWIN];        // window starts (current step)
__device__ float g_thresh[BATCH];               // mean + 1.48*std (current step)

typedef unsigned long long u64;

union F2U { float2 f; u64 u; };

__device__ __forceinline__ u64 fma2(u64 a, u64 b, u64 c) {
    u64 d;
    asm("fma.rn.f32x2 %0, %1, %2, %3;" : "=l"(d) : "l"(a), "l"(b), "l"(c));
    return d;
}

__device__ __forceinline__ float sigmoidf_(float x) {
    return 1.f / (1.f + __expf(-x));
}

// ---------------- threefry2x32 (exact JAX schedule) ----------------
__device__ __forceinline__ uint2 tf2x32(unsigned k0, unsigned k1, unsigned x0, unsigned x1) {
    unsigned ks2 = k0 ^ k1 ^ 0x1BD11BDAu;
    x0 += k0; x1 += k1;
#define TFR(d) { x0 += x1; x1 = __funnelshift_l(x1, x1, d); x1 ^= x0; }
    TFR(13) TFR(15) TFR(26) TFR(6)
    x0 += k1; x1 += ks2 + 1u;
    TFR(17) TFR(29) TFR(16) TFR(24)
    x0 += ks2; x1 += k0 + 2u;
    TFR(13) TFR(15) TFR(26) TFR(6)
    x0 += k0; x1 += k1 + 3u;
    TFR(17) TFR(29) TFR(16) TFR(24)
    x0 += k1; x1 += ks2 + 4u;
    TFR(13) TFR(15) TFR(26) TFR(6)
    x0 += ks2; x1 += k0 + 5u;
#undef TFR
    return make_uint2(x0, x1);
}

// ---------------- kernels ----------------

__global__ void copy_x_kernel(const float* __restrict__ x) {
    int i = blockIdx.x * blockDim.x + threadIdx.x;
    if (i < BATCH * SEQ) {
        int b = i / SEQ, t = i % SEQ;
        g_x[b * XSTRIDE + t] = x[i];
    }
}

__global__ void stats_kernel(int T) {
    int b = blockIdx.x;
    float s = 0.f, ss = 0.f;
    for (int t = threadIdx.x; t < T; t += blockDim.x) {
        float v = g_x[b * XSTRIDE + t];
        s += v; ss += v * v;
    }
    __shared__ float rs[256], rss[256];
    rs[threadIdx.x] = s; rss[threadIdx.x] = ss;
    __syncthreads();
    for (int o = 128; o > 0; o >>= 1) {
        if (threadIdx.x < o) { rs[threadIdx.x] += rs[threadIdx.x + o]; rss[threadIdx.x] += rss[threadIdx.x + o]; }
        __syncthreads();
    }
    if (threadIdx.x == 0) {
        float mean = rs[0] / (float)T;
        float var  = (rss[0] - (float)T * mean * mean) / (float)(T - 1);
        g_thresh[b] = mean + 1.48f * sqrtf(fmaxf(var, 0.f));
    }
}

// starts = jax.random.randint(fold_in(key(42), step), (64,64), 0, span)
__global__ void starts_kernel(int step, unsigned span) {
    int j = blockIdx.x * blockDim.x + threadIdx.x;
    if (j >= BATCH * NWIN) return;
    uint2 key = tf2x32(0u, 42u, 0u, (unsigned)step);       // fold_in
    uint2 s0  = tf2x32(key.x, key.y, 0u, 2u);              // split counts (0,2)
    uint2 s1  = tf2x32(key.x, key.y, 1u, 3u);              // split counts (1,3)
    // k1 = (s0.x, s1.x), k2 = (s0.y, s1.y)
    unsigned hi, lo;
    if (j < 2048) {
        hi = tf2x32(s0.x, s1.x, (unsigned)j, (unsigned)j + 2048u).x;
        lo = tf2x32(s0.y, s1.y, (unsigned)j, (unsigned)j + 2048u).x;
    } else {
        hi = tf2x32(s0.x, s1.x, (unsigned)j - 2048u, (unsigned)j).y;
        lo = tf2x32(s0.y, s1.y, (unsigned)j - 2048u, (unsigned)j).y;
    }
    unsigned m = 65536u % span;
    m = (m * m) % span;
    unsigned off = ((hi % span) * m + (lo % span)) % span;
    g_starts[j] = (int)off;
}

// Global GRU: one CTA per batch element; thread t owns gate row t (r:0-127, z:128-255, n:256-383)
__global__ void __launch_bounds__(384, 1) gru_global_kernel(
    const float* __restrict__ Wi, const float* __restrict__ bi,
    const float* __restrict__ Wh, const float* __restrict__ bh,
    int T_steps, int init_zero)
{
    int b = blockIdx.x, t = threadIdx.x;
    __shared__ __align__(16) float h_s[DM];
    __shared__ float r_s[DM], z_s[DM];

    u64 w[64];
    {
        const float2* wr = (const float2*)(Wh + t * DM);
#pragma unroll
        for (int k = 0; k < 64; k++) { F2U u; u.f = __ldg(wr + k); w[k] = u.u; }
    }
    float wi  = __ldg(Wi + t);
    float bit = __ldg(bi + t);
    float bht = __ldg(bh + t);
    if (t < DM) h_s[t] = init_zero ? 0.f : g_H[b * DM + t];
    __syncthreads();

    const float* xb = g_x + b * XSTRIDE;

    for (int step = 0; step < T_steps; step++) {
        float xt = __ldg(xb + step);
        u64 acc0 = 0ull, acc1 = 0ull;
#pragma unroll
        for (int k4 = 0; k4 < 32; k4++) {
            float4 hv = ((const float4*)h_s)[k4];
            F2U ua, ub;
            ua.f = make_float2(hv.x, hv.y);
            ub.f = make_float2(hv.z, hv.w);
            acc0 = fma2(w[2 * k4],     ua.u, acc0);
            acc1 = fma2(w[2 * k4 + 1], ub.u, acc1);
        }
        F2U a0, a1; a0.u = acc0; a1.u = acc1;
        float gh = a0.f.x + a0.f.y + a1.f.x + a1.f.y + bht;
        float gi = xt * wi + bit;

        if (t < 128) {
            r_s[t] = sigmoidf_(gi + gh);
        } else if (t < 256) {
            z_s[t - 128] = sigmoidf_(gi + gh);
        }
        __syncthreads();
        if (t >= 256) {
            int j = t - 256;
            float n = tanhf(gi + r_s[j] * gh);
            float z = z_s[j];
            h_s[j] = (1.f - z) * n + z * h_s[j];
        }
        __syncthreads();
    }
    if (t < DM) g_H[b * DM + t] = h_s[t];
}

// Window GRU: one CTA handles WG=4 windows; thread t owns gate row t for all 4 windows.
// h stored as h2[k2][g] (float2 over k) so one LDS.128 feeds 2 windows.
__global__ void __launch_bounds__(384, 1) gru_window_kernel(
    const float* __restrict__ Wi, const float* __restrict__ bi,
    const float* __restrict__ Wh, const float* __restrict__ bh)
{
    int cta = blockIdx.x, t = threadIdx.x;
    __shared__ __align__(16) float2 h2[64][WG];
    __shared__ float r_s[WG][DM], z_s[WG][DM];
    __shared__ float x_s[WG][WLEN];
    __shared__ int   st_s[WG];

    u64 w[64];
    {
        const float2* wr = (const float2*)(Wh + t * DM);
#pragma unroll
        for (int k = 0; k < 64; k++) { F2U u; u.f = __ldg(wr + k); w[k] = u.u; }
    }
    float wi  = __ldg(Wi + t);
    float bit = __ldg(bi + t);
    float bht = __ldg(bh + t);

    if (t < WG) st_s[t] = g_starts[cta * WG + t];
    for (int idx = t; idx < 64 * WG * 2; idx += G3) ((float*)h2)[idx] = 0.f;
    __syncthreads();
    for (int idx = t; idx < WG * WLEN; idx += G3) {
        int g = idx >> 6, kk = idx & 63;
        int b = (cta * WG + g) >> 6;
        x_s[g][kk] = g_x[b * XSTRIDE + st_s[g] + kk];
    }
    __syncthreads();

    for (int step = 0; step < WLEN; step++) {
        u64 acc[WG];
#pragma unroll
        for (int g = 0; g < WG; g++) acc[g] = 0ull;
#pragma unroll
        for (int k = 0; k < 64; k++) {
            float4 p = *(const float4*)&h2[k][0];   // windows 0,1 (k-pair each)
            float4 q = *(const float4*)&h2[k][2];   // windows 2,3
            F2U u0, u1, u2, u3;
            u0.f = make_float2(p.x, p.y); u1.f = make_float2(p.z, p.w);
            u2.f = make_float2(q.x, q.y); u3.f = make_float2(q.z, q.w);
            acc[0] = fma2(w[k], u0.u, acc[0]);
            acc[1] = fma2(w[k], u1.u, acc[1]);
            acc[2] = fma2(w[k], u2.u, acc[2]);
            acc[3] = fma2(w[k], u3.u, acc[3]);
        }
        float gh[WG], gi[WG];
#pragma unroll
        for (int g = 0; g < WG; g++) {
            F2U a; a.u = acc[g];
            gh[g] = a.f.x + a.f.y + bht;
            gi[g] = x_s[g][step] * wi + bit;
        }
        if (t < 128) {
#pragma unroll
            for (int g = 0; g < WG; g++) r_s[g][t] = sigmoidf_(gi[g] + gh[g]);
        } else if (t < 256) {
#pragma unroll
            for (int g = 0; g < WG; g++) z_s[g][t - 128] = sigmoidf_(gi[g] + gh[g]);
        }
        __syncthreads();
        if (t >= 256) {
            int j = t - 256;
#pragma unroll
            for (int g = 0; g < WG; g++) {
                float n = tanhf(gi[g] + r_s[g][j] * gh[g]);
                float z = z_s[g][j];
                float* hp = (float*)&h2[j >> 1][g];
                float hold = hp[j & 1];
                hp[j & 1] = (1.f - z) * n + z * hold;
            }
        }
        __syncthreads();
    }
    if (t < DM) {
#pragma unroll
        for (int g = 0; g < WG; g++) {
            g_S[(cta * WG + g) * DM + t] = ((const float*)&h2[t >> 1][g])[t & 1];
        }
    }
}

// Attention + event gather + heads; append y; write outputs
__global__ void finalize_kernel(const float* __restrict__ Wd, const float* __restrict__ bd,
                                const float* __restrict__ Wc, const float* __restrict__ bc,
                                int step, float* __restrict__ out, int out_size)
{
    int b = blockIdx.x, t = threadIdx.x;  // 128 threads
    __shared__ float H_sh[DM];
    __shared__ float e_s[NWIN];
    __shared__ float red[DM];
    __shared__ float qred[NWIN];
    __shared__ float se_sh;

    H_sh[t] = g_H[b * DM + t];
    __syncthreads();

    if (t < NWIN) {
        const float* S = g_S + (b * NWIN + t) * DM;
        float d = 0.f;
#pragma unroll 4
        for (int h = 0; h < DM; h++) d += H_sh[h] * S[h];
        e_s[t] = d;
    }
    __syncthreads();

    if (t == 0) {
        float mx = -1e30f;
        for (int m = 0; m < NWIN; m++) mx = fmaxf(mx, e_s[m]);
        float se = 0.f;
        for (int m = 0; m < NWIN; m++) { float e = __expf(e_s[m] - mx); e_s[m] = e; se += e; }
        se_sh = se;
    }
    __syncthreads();

    red[t] = H_sh[t] * __ldg(Wd + t);
    if (t < NWIN) {
        int idx = g_starts[b * NWIN + t] + WLEN;
        float q = (g_x[b * XSTRIDE + idx] > g_thresh[b]) ? 1.f : 0.f;
        qred[t] = q * e_s[t];
    }
    __syncthreads();

    for (int o = 64; o > 0; o >>= 1) {
        if (t < o) red[t] += red[t + o];
        if (o <= 32 && t < o) qred[t] += qred[t + o];
        __syncthreads();
    }

    if (t == 0) {
        float oval = red[0] + __ldg(bd);
        float s = qred[0] / se_sh;
        float u = sigmoidf_(s * __ldg(Wc) + __ldg(bc));
        float y = oval + u;
        g_x[b * XSTRIDE + SEQ + step] = y;
        out[b * PRED + step] = y;
        if (out_size >= 2 * BATCH * PRED) out[BATCH * PRED + b * PRED + step] = u;
    }
}

// ---------------- launcher ----------------
extern "C" void kernel_launch(void* const* d_in, const int* in_sizes, int n_in,
                              void* d_out, int out_size) {
    const float* batch_x = (const float*)d_in[0];
    const float* Wi_g = (const float*)d_in[4];
    const float* Wh_g = (const float*)d_in[5];
    const float* bi_g = (const float*)d_in[6];
    const float* bh_g = (const float*)d_in[7];
    const float* Wi_w = (const float*)d_in[8];
    const float* Wh_w = (const float*)d_in[9];
    const float* bi_w = (const float*)d_in[10];
    const float* bh_w = (const float*)d_in[11];
    const float* Wd   = (const float*)d_in[12];
    const float* bd   = (const float*)d_in[13];
    const float* Wc   = (const float*)d_in[16];
    const float* bc   = (const float*)d_in[17];
    float* out = (float*)d_out;

    copy_x_kernel<<<(BATCH * SEQ + 255) / 256, 256>>>(batch_x);

    for (int i = 0; i < PRED; i++) {
        int T = SEQ + i;
        stats_kernel<<<BATCH, 256>>>(T);
        int steps = (i == 0) ? SEQ : (T - 1);
        gru_global_kernel<<<BATCH, G3>>>(Wi_g, bi_g, Wh_g, bh_g, steps, (i == 0) ? 1 : 0);
        starts_kernel<<<(BATCH * NWIN + 255) / 256, 256>>>(i, (unsigned)(T - WLEN));
        gru_window_kernel<<<(BATCH * NWIN) / WG, G3>>>(Wi_w, bi_w, Wh_w, bh_w);
        finalize_kernel<<<BATCH, DM>>>(Wd, bd, Wc, bc, i, out, out_size);
    }
}

// round 5
// speedup vs baseline: 1.8403x; 1.8403x over previous
#include <cuda_runtime.h>
#include <cstdint>

#define BATCH   64
#define SEQ     2048
#define DM      128
#define G3      384
#define XSTRIDE 2052
#define NWIN    64
#define WLEN    64
#define PRED    4
#define WG      4
#define NWORK   84
#define NCTA    (BATCH + NWORK)   // 148 CTAs, all resident
#define NGROUPS 256               // 1024 windows / WG per pred step

// ---------------- persistent device scratch (no allocs allowed) ----------------
__device__ float g_x[BATCH * XSTRIDE];            // sequence extended with predictions
__device__ float g_H4[PRED * BATCH * DM];         // global GRU state per pred step
__device__ float g_S4[PRED * BATCH * NWIN * DM];  // window GRU final states per pred step
__device__ int   g_hcnt;                          // H publishes (64 per phase)
__device__ int   g_scnt[PRED];                    // window groups done per pred (-> 256)
__device__ int   g_ycnt;                          // y publishes (64 per pred step)

typedef unsigned long long u64;

union F2U { float2 f; u64 u; };

__device__ __forceinline__ u64 fma2(u64 a, u64 b, u64 c) {
    u64 d;
    asm("fma.rn.f32x2 %0, %1, %2, %3;" : "=l"(d) : "l"(a), "l"(b), "l"(c));
    return d;
}

__device__ __forceinline__ float sigmoidf_(float x) {
    return 1.f / (1.f + __expf(-x));
}

// ---------------- threefry2x32 (exact JAX schedule) ----------------
__device__ __forceinline__ uint2 tf2x32(unsigned k0, unsigned k1, unsigned x0, unsigned x1) {
    unsigned ks2 = k0 ^ k1 ^ 0x1BD11BDAu;
    x0 += k0; x1 += k1;
#define TFR(d) { x0 += x1; x1 = __funnelshift_l(x1, x1, d); x1 ^= x0; }
    TFR(13) TFR(15) TFR(26) TFR(6)
    x0 += k1; x1 += ks2 + 1u;
    TFR(17) TFR(29) TFR(16) TFR(24)
    x0 += ks2; x1 += k0 + 2u;
    TFR(13) TFR(15) TFR(26) TFR(6)
    x0 += k0; x1 += k1 + 3u;
    TFR(17) TFR(29) TFR(16) TFR(24)
    x0 += k1; x1 += ks2 + 4u;
    TFR(13) TFR(15) TFR(26) TFR(6)
    x0 += ks2; x1 += k0 + 5u;
#undef TFR
    return make_uint2(x0, x1);
}

// starts[j] for pred `step`, window j in [0,4096), span = T - WLEN
__device__ __forceinline__ int rand_start(int step, int j, unsigned span) {
    uint2 key = tf2x32(0u, 42u, 0u, (unsigned)step);
    uint2 s0  = tf2x32(key.x, key.y, 0u, 2u);
    uint2 s1  = tf2x32(key.x, key.y, 1u, 3u);
    unsigned hi, lo;
    if (j < 2048) {
        hi = tf2x32(s0.x, s1.x, (unsigned)j, (unsigned)j + 2048u).x;
        lo = tf2x32(s0.y, s1.y, (unsigned)j, (unsigned)j + 2048u).x;
    } else {
        hi = tf2x32(s0.x, s1.x, (unsigned)j - 2048u, (unsigned)j).y;
        lo = tf2x32(s0.y, s1.y, (unsigned)j - 2048u, (unsigned)j).y;
    }
    unsigned m = 65536u % span;
    m = (m * m) % span;
    return (int)(((hi % span) * m + (lo % span)) % span);
}

// acquire-spin: thread 0 polls counter (L2, volatile), whole CTA proceeds after
__device__ __forceinline__ void wait_ctr(int* ctr, int v) {
    __syncthreads();
    if (threadIdx.x == 0) {
        while (*(volatile int*)ctr < v) { __nanosleep(64); }
    }
    __syncthreads();
}

// ---------------- kernels ----------------

__global__ void copy_x_kernel(const float* __restrict__ x) {
    int i = blockIdx.x * blockDim.x + threadIdx.x;
    if (i == 0) {
        g_hcnt = 0; g_ycnt = 0;
        for (int p = 0; p < PRED; p++) g_scnt[p] = 0;
    }
    if (i < BATCH * SEQ) {
        int b = i / SEQ, t = i % SEQ;
        g_x[b * XSTRIDE + t] = x[i];
    }
}

// ============ global-GRU path (CTAs 0..63) ============
__device__ void global_path(int b,
    const float* __restrict__ Wi, const float* __restrict__ bi,
    const float* __restrict__ Wh, const float* __restrict__ bh)
{
    int t = threadIdx.x;
    __shared__ __align__(16) float h_s[DM];
    __shared__ float r_s[DM], z_s[DM];

    u64 w[64];
    {
        const float2* wr = (const float2*)(Wh + t * DM);
#pragma unroll
        for (int k = 0; k < 64; k++) { F2U u; u.f = __ldg(wr + k); w[k] = u.u; }
    }
    float wi  = __ldg(Wi + t);
    float bit = __ldg(bi + t);
    float bht = __ldg(bh + t);
    if (t < DM) h_s[t] = 0.f;
    __syncthreads();

    const float* xb = g_x + b * XSTRIDE;
    const int Lp[PRED] = {2048, 2048, 2049, 2050};

    for (int p = 0; p < PRED; p++) {
        if (p >= 2) wait_ctr(&g_ycnt, BATCH * (p - 1));  // y_0..y_{p-2} present
        int L = Lp[p];
        for (int step = 0; step < L; step++) {
            float xt = (step < SEQ) ? __ldg(xb + step) : __ldcg(xb + step);
            u64 acc0 = 0ull, acc1 = 0ull;
#pragma unroll
            for (int k4 = 0; k4 < 32; k4++) {
                float4 hv = ((const float4*)h_s)[k4];
                F2U ua, ub;
                ua.f = make_float2(hv.x, hv.y);
                ub.f = make_float2(hv.z, hv.w);
                acc0 = fma2(w[2 * k4],     ua.u, acc0);
                acc1 = fma2(w[2 * k4 + 1], ub.u, acc1);
            }
            F2U a0, a1; a0.u = acc0; a1.u = acc1;
            float gh = a0.f.x + a0.f.y + a1.f.x + a1.f.y + bht;
            float gi = xt * wi + bit;

            if (t < 128) {
                r_s[t] = sigmoidf_(gi + gh);
            } else if (t < 256) {
                z_s[t - 128] = sigmoidf_(gi + gh);
            }
            __syncthreads();
            if (t >= 256) {
                int j = t - 256;
                float n = tanhf(gi + r_s[j] * gh);
                float z = z_s[j];
                h_s[j] = (1.f - z) * n + z * h_s[j];
            }
            __syncthreads();
        }
        if (t < DM) g_H4[p * BATCH * DM + b * DM + t] = h_s[t];
        __threadfence();
        __syncthreads();
        if (t == 0) atomicAdd(&g_hcnt, 1);
    }
}

// ============ worker path (CTAs 64..147): windows + stats + finalize ============
__device__ void worker_path(int w,
    const float* __restrict__ Wi, const float* __restrict__ bi,
    const float* __restrict__ Wh, const float* __restrict__ bh,
    const float* __restrict__ Wd, const float* __restrict__ bd,
    const float* __restrict__ Wc, const float* __restrict__ bc,
    float* __restrict__ out, int out_size)
{
    int t = threadIdx.x;
    __shared__ __align__(16) float2 h2[64][WG];
    __shared__ float r_s[WG][DM], z_s[WG][DM];
    __shared__ float x_s[WG][WLEN];
    __shared__ int   st_s[WG];
    __shared__ float rs[256], rss[256];
    __shared__ float thresh_sh;
    __shared__ float H_sh[DM], e_s[NWIN], red[DM], qred[NWIN], se_sh;
    __shared__ int   starts_sh[NWIN];

    u64 wr_[64];
    {
        const float2* wr2 = (const float2*)(Wh + t * DM);
#pragma unroll
        for (int k = 0; k < 64; k++) { F2U u; u.f = __ldg(wr2 + k); wr_[k] = u.u; }
    }
    float wi  = __ldg(Wi + t);
    float bit = __ldg(bi + t);
    float bht = __ldg(bh + t);

    for (int p = 0; p < PRED; p++) {
        unsigned span = (unsigned)(SEQ + p - WLEN);  // 1984+p

        // ---- window groups of this pred (need y_{p-2}) ----
        if (p >= 2) wait_ctr(&g_ycnt, BATCH * (p - 1));
        int ngroups = 0;
        for (int g = (w + 4) % NWORK; g < NGROUPS; g += NWORK) {
            int b = g >> 4;                      // 16 groups per batch
            if (t < WG) st_s[t] = rand_start(p, b * NWIN + ((g & 15) * WG + t), span);
            for (int idx = t; idx < 64 * WG * 2; idx += G3) ((float*)h2)[idx] = 0.f;
            __syncthreads();
            for (int idx = t; idx < WG * WLEN; idx += G3) {
                int gg = idx >> 6, kk = idx & 63;
                x_s[gg][kk] = __ldcg(&g_x[b * XSTRIDE + st_s[gg] + kk]);
            }
            __syncthreads();

            for (int step = 0; step < WLEN; step++) {
                u64 acc[WG];
#pragma unroll
                for (int gg = 0; gg < WG; gg++) acc[gg] = 0ull;
#pragma unroll
                for (int k = 0; k < 64; k++) {
                    float4 pp = *(const float4*)&h2[k][0];
                    float4 qq = *(const float4*)&h2[k][2];
                    F2U u0, u1, u2, u3;
                    u0.f = make_float2(pp.x, pp.y); u1.f = make_float2(pp.z, pp.w);
                    u2.f = make_float2(qq.x, qq.y); u3.f = make_float2(qq.z, qq.w);
                    acc[0] = fma2(wr_[k], u0.u, acc[0]);
                    acc[1] = fma2(wr_[k], u1.u, acc[1]);
                    acc[2] = fma2(wr_[k], u2.u, acc[2]);
                    acc[3] = fma2(wr_[k], u3.u, acc[3]);
                }
                float gh[WG], gi[WG];
#pragma unroll
                for (int gg = 0; gg < WG; gg++) {
                    F2U a; a.u = acc[gg];
                    gh[gg] = a.f.x + a.f.y + bht;
                    gi[gg] = x_s[gg][step] * wi + bit;
                }
                if (t < 128) {
#pragma unroll
                    for (int gg = 0; gg < WG; gg++) r_s[gg][t] = sigmoidf_(gi[gg] + gh[gg]);
                } else if (t < 256) {
#pragma unroll
                    for (int gg = 0; gg < WG; gg++) z_s[gg][t - 128] = sigmoidf_(gi[gg] + gh[gg]);
                }
                __syncthreads();
                if (t >= 256) {
                    int j = t - 256;
#pragma unroll
                    for (int gg = 0; gg < WG; gg++) {
                        float n = tanhf(gi[gg] + r_s[gg][j] * gh[gg]);
                        float z = z_s[gg][j];
                        float* hp = (float*)&h2[j >> 1][gg];
                        float hold = hp[j & 1];
                        hp[j & 1] = (1.f - z) * n + z * hold;
                    }
                }
                __syncthreads();
            }
            if (t < DM) {
#pragma unroll
                for (int gg = 0; gg < WG; gg++) {
                    g_S4[(p * BATCH * NWIN + g * WG + gg) * DM + t] =
                        ((const float*)&h2[t >> 1][gg])[t & 1];
                }
            }
            __syncthreads();
            ngroups++;
        }
        __threadfence();
        __syncthreads();
        if (t == 0 && ngroups) atomicAdd(&g_scnt[p], ngroups);

        // ---- stats + finalize for batch b = w (first 64 workers) ----
        if (w < BATCH) {
            int b = w;
            int T = SEQ + p;
            if (p >= 1) wait_ctr(&g_ycnt, BATCH * p);   // need y_{p-1}

            float s = 0.f, ss = 0.f;
            if (t < 256) {
                for (int i = t; i < T; i += 256) {
                    float v = (i < SEQ) ? __ldg(&g_x[b * XSTRIDE + i])
                                        : __ldcg(&g_x[b * XSTRIDE + i]);
                    s += v; ss += v * v;
                }
                rs[t] = s; rss[t] = ss;
            }
            __syncthreads();
            for (int o = 128; o > 0; o >>= 1) {
                if (t < o) { rs[t] += rs[t + o]; rss[t] += rss[t + o]; }
                __syncthreads();
            }
            if (t == 0) {
                float mean = rs[0] / (float)T;
                float var  = (rss[0] - (float)T * mean * mean) / (float)(T - 1);
                thresh_sh = mean + 1.48f * sqrtf(fmaxf(var, 0.f));
            }

            wait_ctr(&g_hcnt, BATCH * (p + 1));   // H_p published (all batches)
            wait_ctr(&g_scnt[p], NGROUPS);        // all windows of pred p done

            if (t < NWIN) starts_sh[t] = rand_start(p, b * NWIN + t, span);
            if (t < DM)   H_sh[t] = __ldcg(&g_H4[p * BATCH * DM + b * DM + t]);
            __syncthreads();

            if (t < NWIN) {
                const float* S = g_S4 + (p * BATCH * NWIN + b * NWIN + t) * DM;
                float d = 0.f;
#pragma unroll 4
                for (int h = 0; h < DM; h++) d += H_sh[h] * __ldcg(S + h);
                e_s[t] = d;
            }
            __syncthreads();

            if (t == 0) {
                float mx = -1e30f;
                for (int m = 0; m < NWIN; m++) mx = fmaxf(mx, e_s[m]);
                float se = 0.f;
                for (int m = 0; m < NWIN; m++) { float e = __expf(e_s[m] - mx); e_s[m] = e; se += e; }
                se_sh = se;
            }
            __syncthreads();

            if (t < DM) red[t] = H_sh[t] * __ldg(Wd + t);
            if (t < NWIN) {
                int idx = starts_sh[t] + WLEN;
                float q = (__ldcg(&g_x[b * XSTRIDE + idx]) > thresh_sh) ? 1.f : 0.f;
                qred[t] = q * e_s[t];
            }
            __syncthreads();

            for (int o = 64; o > 0; o >>= 1) {
                if (t < o) red[t] += red[t + o];
                if (o <= 32 && t < o) qred[t] += qred[t + o];
                __syncthreads();
            }

            if (t == 0) {
                float oval = red[0] + __ldg(bd);
                float sc = qred[0] / se_sh;
                float u = sigmoidf_(sc * __ldg(Wc) + __ldg(bc));
                float y = oval + u;
                g_x[b * XSTRIDE + SEQ + p] = y;
                out[b * PRED + p] = y;
                if (out_size >= 2 * BATCH * PRED) out[BATCH * PRED + b * PRED + p] = u;
                __threadfence();
                atomicAdd(&g_ycnt, 1);
            }
            __syncthreads();
        }
    }
}

__global__ void __launch_bounds__(G3, 1) persist_kernel(
    const float* __restrict__ Wi_g, const float* __restrict__ bi_g,
    const float* __restrict__ Wh_g, const float* __restrict__ bh_g,
    const float* __restrict__ Wi_w, const float* __restrict__ bi_w,
    const float* __restrict__ Wh_w, const float* __restrict__ bh_w,
    const float* __restrict__ Wd,   const float* __restrict__ bd,
    const float* __restrict__ Wc,   const float* __restrict__ bc,
    float* __restrict__ out, int out_size)
{
    int cta = blockIdx.x;
    if (cta < BATCH) {
        global_path(cta, Wi_g, bi_g, Wh_g, bh_g);
    } else {
        worker_path(cta - BATCH, Wi_w, bi_w, Wh_w, bh_w, Wd, bd, Wc, bc, out, out_size);
    }
}

// ---------------- launcher (default stream only, like the passing R1 setup) ----------------
extern "C" void kernel_launch(void* const* d_in, const int* in_sizes, int n_in,
                              void* d_out, int out_size) {
    const float* batch_x = (const float*)d_in[0];
    const float* Wi_g = (const float*)d_in[4];
    const float* Wh_g = (const float*)d_in[5];
    const float* bi_g = (const float*)d_in[6];
    const float* bh_g = (const float*)d_in[7];
    const float* Wi_w = (const float*)d_in[8];
    const float* Wh_w = (const float*)d_in[9];
    const float* bi_w = (const float*)d_in[10];
    const float* bh_w = (const float*)d_in[11];
    const float* Wd   = (const float*)d_in[12];
    const float* bd   = (const float*)d_in[13];
    const float* Wc   = (const float*)d_in[16];
    const float* bc   = (const float*)d_in[17];
    float* out = (float*)d_out;

    copy_x_kernel<<<(BATCH * SEQ + 255) / 256, 256>>>(batch_x);
    persist_kernel<<<NCTA, G3>>>(Wi_g, bi_g, Wh_g, bh_g,
                                 Wi_w, bi_w, Wh_w, bh_w,
                                 Wd, bd, Wc, bc, out, out_size);
}

// round 6
// speedup vs baseline: 1.8451x; 1.0026x over previous
#include <cuda_runtime.h>
#include <cstdint>

#define BATCH   64
#define SEQ     2048
#define DM      128
#define G3      384
#define XSTRIDE 2052
#define NWIN    64
#define WLEN    64
#define PRED    4
#define WG      4
#define NWORK   84
#define NCTA    (BATCH + NWORK)   // 148 CTAs, all resident
#define NGROUPS 256               // 1024 windows / WG per pred step

// ---------------- persistent device scratch (no allocs allowed) ----------------
__device__ float g_x[BATCH * XSTRIDE];            // sequence extended with predictions
__device__ float g_H4[PRED * BATCH * DM];         // global GRU state per pred step
__device__ float g_S4[PRED * BATCH * NWIN * DM];  // window GRU final states per pred step
__device__ int   g_hcnt;                          // H publishes (64 per phase)
__device__ int   g_scnt[PRED];                    // window groups done per pred (-> 256)
__device__ int   g_ycnt;                          // y publishes (64 per pred step)

typedef unsigned long long u64;

union F2U { float2 f; u64 u; };

__device__ __forceinline__ u64 fma2(u64 a, u64 b, u64 c) {
    u64 d;
    asm("fma.rn.f32x2 %0, %1, %2, %3;" : "=l"(d) : "l"(a), "l"(b), "l"(c));
    return d;
}

__device__ __forceinline__ float sigmoidf_(float x) {
    return 1.f / (1.f + __expf(-x));
}

// ---------------- threefry2x32 (exact JAX schedule) ----------------
__device__ __forceinline__ uint2 tf2x32(unsigned k0, unsigned k1, unsigned x0, unsigned x1) {
    unsigned ks2 = k0 ^ k1 ^ 0x1BD11BDAu;
    x0 += k0; x1 += k1;
#define TFR(d) { x0 += x1; x1 = __funnelshift_l(x1, x1, d); x1 ^= x0; }
    TFR(13) TFR(15) TFR(26) TFR(6)
    x0 += k1; x1 += ks2 + 1u;
    TFR(17) TFR(29) TFR(16) TFR(24)
    x0 += ks2; x1 += k0 + 2u;
    TFR(13) TFR(15) TFR(26) TFR(6)
    x0 += k0; x1 += k1 + 3u;
    TFR(17) TFR(29) TFR(16) TFR(24)
    x0 += k1; x1 += ks2 + 4u;
    TFR(13) TFR(15) TFR(26) TFR(6)
    x0 += ks2; x1 += k0 + 5u;
#undef TFR
    return make_uint2(x0, x1);
}

// starts[j] for pred `step`, window j in [0,4096), span = T - WLEN
__device__ __forceinline__ int rand_start(int step, int j, unsigned span) {
    uint2 key = tf2x32(0u, 42u, 0u, (unsigned)step);
    uint2 s0  = tf2x32(key.x, key.y, 0u, 2u);
    uint2 s1  = tf2x32(key.x, key.y, 1u, 3u);
    unsigned hi, lo;
    if (j < 2048) {
        hi = tf2x32(s0.x, s1.x, (unsigned)j, (unsigned)j + 2048u).x;
        lo = tf2x32(s0.y, s1.y, (unsigned)j, (unsigned)j + 2048u).x;
    } else {
        hi = tf2x32(s0.x, s1.x, (unsigned)j - 2048u, (unsigned)j).y;
        lo = tf2x32(s0.y, s1.y, (unsigned)j - 2048u, (unsigned)j).y;
    }
    unsigned m = 65536u % span;
    m = (m * m) % span;
    return (int)(((hi % span) * m + (lo % span)) % span);
}

// acquire-spin: thread 0 polls counter (L2, volatile), whole CTA proceeds after
__device__ __forceinline__ void wait_ctr(int* ctr, int v) {
    __syncthreads();
    if (threadIdx.x == 0) {
        while (*(volatile int*)ctr < v) { __nanosleep(64); }
    }
    __syncthreads();
}

// ---------------- kernels ----------------

__global__ void copy_x_kernel(const float* __restrict__ x) {
    int i = blockIdx.x * blockDim.x + threadIdx.x;
    if (i == 0) {
        g_hcnt = 0; g_ycnt = 0;
        for (int p = 0; p < PRED; p++) g_scnt[p] = 0;
    }
    if (i < BATCH * SEQ) {
        int b = i / SEQ, t = i % SEQ;
        g_x[b * XSTRIDE + t] = x[i];
    }
}

// ============ global-GRU path (CTAs 0..63) ============
// Threads 0..255: (row j in [0,128), k-half c) compute BOTH r-gate and n-gate
//   partial dots over 64 k's; halves combined via shfl_xor(16); r and n stay in
//   registers (no smem round-trip for r).
// Threads 256..383: z-gate rows (full-k dot), publish z via smem.
__device__ void global_path(int b,
    const float* __restrict__ Wi, const float* __restrict__ bi,
    const float* __restrict__ Wh, const float* __restrict__ bh)
{
    int t = threadIdx.x;
    int wid = t >> 5, lane = t & 31;
    bool is_rn = (wid < 8);

    __shared__ __align__(16) float h_s[DM];
    __shared__ float z_s[DM];

    u64 w0[32], w1[32];
    int j, c;
    float wi_a, bi_a, bh_a;       // r-gate (rn) or z-gate (z) scalars
    float wi_n = 0.f, bi_n = 0.f, bh_n = 0.f;

    if (is_rn) {
        j = (wid << 4) + (lane & 15);
        c = lane >> 4;
        const float2* pr = (const float2*)(Wh + j * DM + c * 64);
        const float2* pn = (const float2*)(Wh + (256 + j) * DM + c * 64);
#pragma unroll
        for (int k = 0; k < 32; k++) { F2U u; u.f = __ldg(pr + k); w0[k] = u.u; }
#pragma unroll
        for (int k = 0; k < 32; k++) { F2U u; u.f = __ldg(pn + k); w1[k] = u.u; }
        wi_a = __ldg(Wi + j);       bi_a = __ldg(bi + j);       bh_a = __ldg(bh + j);
        wi_n = __ldg(Wi + 256 + j); bi_n = __ldg(bi + 256 + j); bh_n = __ldg(bh + 256 + j);
    } else {
        j = t - 256;
        c = 0;
        const float2* pz = (const float2*)(Wh + (128 + j) * DM);
#pragma unroll
        for (int k = 0; k < 32; k++) { F2U u; u.f = __ldg(pz + k);      w0[k] = u.u; }
#pragma unroll
        for (int k = 0; k < 32; k++) { F2U u; u.f = __ldg(pz + 32 + k); w1[k] = u.u; }
        wi_a = __ldg(Wi + 128 + j); bi_a = __ldg(bi + 128 + j); bh_a = __ldg(bh + 128 + j);
    }

    if (t < DM) h_s[t] = 0.f;
    __syncthreads();

    const float* xb = g_x + b * XSTRIDE;
    const int Lp[PRED] = {2048, 2048, 2049, 2050};

    for (int p = 0; p < PRED; p++) {
        if (p >= 2) wait_ctr(&g_ycnt, BATCH * (p - 1));  // y_0..y_{p-2} present
        int L = Lp[p];
        for (int step = 0; step < L; step++) {
            float xt = (step < SEQ) ? __ldg(xb + step) : __ldcg(xb + step);
            float h_old = h_s[j];

            float r_loc = 0.f, n_loc = 0.f;
            if (is_rn) {
                const float4* hp = (const float4*)(h_s + c * 64);
                u64 a0 = 0ull, a1 = 0ull, a2 = 0ull, a3 = 0ull;
#pragma unroll
                for (int k4 = 0; k4 < 16; k4++) {
                    float4 hv = hp[k4];
                    F2U ua, ub;
                    ua.f = make_float2(hv.x, hv.y);
                    ub.f = make_float2(hv.z, hv.w);
                    a0 = fma2(w0[2 * k4],     ua.u, a0);
                    a1 = fma2(w0[2 * k4 + 1], ub.u, a1);
                    a2 = fma2(w1[2 * k4],     ua.u, a2);
                    a3 = fma2(w1[2 * k4 + 1], ub.u, a3);
                }
                F2U s0, s1, s2, s3; s0.u = a0; s1.u = a1; s2.u = a2; s3.u = a3;
                float ghr = s0.f.x + s0.f.y + s1.f.x + s1.f.y;
                float ghn = s2.f.x + s2.f.y + s3.f.x + s3.f.y;
                ghr += __shfl_xor_sync(0xffffffffu, ghr, 16);
                ghn += __shfl_xor_sync(0xffffffffu, ghn, 16);
                float gir = xt * wi_a + bi_a;
                float gin = xt * wi_n + bi_n;
                r_loc = sigmoidf_(gir + (ghr + bh_a));
                n_loc = tanhf(gin + r_loc * (ghn + bh_n));
            } else {
                const float4* hp = (const float4*)h_s;
                u64 a0 = 0ull, a1 = 0ull, a2 = 0ull, a3 = 0ull;
#pragma unroll
                for (int k4 = 0; k4 < 16; k4++) {
                    float4 hv = hp[k4];
                    F2U ua, ub;
                    ua.f = make_float2(hv.x, hv.y);
                    ub.f = make_float2(hv.z, hv.w);
                    a0 = fma2(w0[2 * k4],     ua.u, a0);
                    a1 = fma2(w0[2 * k4 + 1], ub.u, a1);
                }
#pragma unroll
                for (int k4 = 0; k4 < 16; k4++) {
                    float4 hv = hp[16 + k4];
                    F2U ua, ub;
                    ua.f = make_float2(hv.x, hv.y);
                    ub.f = make_float2(hv.z, hv.w);
                    a2 = fma2(w1[2 * k4],     ua.u, a2);
                    a3 = fma2(w1[2 * k4 + 1], ub.u, a3);
                }
                F2U s0, s1, s2, s3; s0.u = a0; s1.u = a1; s2.u = a2; s3.u = a3;
                float ghz = s0.f.x + s0.f.y + s1.f.x + s1.f.y
                          + s2.f.x + s2.f.y + s3.f.x + s3.f.y;
                float giz = xt * wi_a + bi_a;
                z_s[j] = sigmoidf_(giz + (ghz + bh_a));
            }
            __syncthreads();   // z_s ready; h_s still old
            if (is_rn) {
                float z = z_s[j];
                float hn = (1.f - z) * n_loc + z * h_old;
                if (c == 0) h_s[j] = hn;
            }
            __syncthreads();   // h_s updated
        }
        if (t < DM) g_H4[p * BATCH * DM + b * DM + t] = h_s[t];
        __threadfence();
        __syncthreads();
        if (t == 0) atomicAdd(&g_hcnt, 1);
    }
}

// ============ worker path (CTAs 64..147): windows + stats + finalize ============
__device__ void worker_path(int w,
    const float* __restrict__ Wi, const float* __restrict__ bi,
    const float* __restrict__ Wh, const float* __restrict__ bh,
    const float* __restrict__ Wd, const float* __restrict__ bd,
    const float* __restrict__ Wc, const float* __restrict__ bc,
    float* __restrict__ out, int out_size)
{
    int t = threadIdx.x;
    __shared__ __align__(16) float2 h2[64][WG];
    __shared__ float r_s[WG][DM], z_s[WG][DM];
    __shared__ float x_s[WG][WLEN];
    __shared__ int   st_s[WG];
    __shared__ float rs[256], rss[256];
    __shared__ float thresh_sh;
    __shared__ float H_sh[DM], e_s[NWIN], red[DM], qred[NWIN], se_sh;
    __shared__ int   starts_sh[NWIN];

    u64 wr_[64];
    {
        const float2* wr2 = (const float2*)(Wh + t * DM);
#pragma unroll
        for (int k = 0; k < 64; k++) { F2U u; u.f = __ldg(wr2 + k); wr_[k] = u.u; }
    }
    float wi  = __ldg(Wi + t);
    float bit = __ldg(bi + t);
    float bht = __ldg(bh + t);

    for (int p = 0; p < PRED; p++) {
        unsigned span = (unsigned)(SEQ + p - WLEN);  // 1984+p

        // ---- window groups of this pred (need y_{p-2}) ----
        if (p >= 2) wait_ctr(&g_ycnt, BATCH * (p - 1));
        int ngroups = 0;
        for (int g = (w + 4) % NWORK; g < NGROUPS; g += NWORK) {
            int b = g >> 4;                      // 16 groups per batch
            if (t < WG) st_s[t] = rand_start(p, b * NWIN + ((g & 15) * WG + t), span);
            for (int idx = t; idx < 64 * WG * 2; idx += G3) ((float*)h2)[idx] = 0.f;
            __syncthreads();
            for (int idx = t; idx < WG * WLEN; idx += G3) {
                int gg = idx >> 6, kk = idx & 63;
                x_s[gg][kk] = __ldcg(&g_x[b * XSTRIDE + st_s[gg] + kk]);
            }
            __syncthreads();

            for (int step = 0; step < WLEN; step++) {
                u64 acc[WG];
#pragma unroll
                for (int gg = 0; gg < WG; gg++) acc[gg] = 0ull;
#pragma unroll
                for (int k = 0; k < 64; k++) {
                    float4 pp = *(const float4*)&h2[k][0];
                    float4 qq = *(const float4*)&h2[k][2];
                    F2U u0, u1, u2, u3;
                    u0.f = make_float2(pp.x, pp.y); u1.f = make_float2(pp.z, pp.w);
                    u2.f = make_float2(qq.x, qq.y); u3.f = make_float2(qq.z, qq.w);
                    acc[0] = fma2(wr_[k], u0.u, acc[0]);
                    acc[1] = fma2(wr_[k], u1.u, acc[1]);
                    acc[2] = fma2(wr_[k], u2.u, acc[2]);
                    acc[3] = fma2(wr_[k], u3.u, acc[3]);
                }
                float gh[WG], gi[WG];
#pragma unroll
                for (int gg = 0; gg < WG; gg++) {
                    F2U a; a.u = acc[gg];
                    gh[gg] = a.f.x + a.f.y + bht;
                    gi[gg] = x_s[gg][step] * wi + bit;
                }
                if (t < 128) {
#pragma unroll
                    for (int gg = 0; gg < WG; gg++) r_s[gg][t] = sigmoidf_(gi[gg] + gh[gg]);
                } else if (t < 256) {
#pragma unroll
                    for (int gg = 0; gg < WG; gg++) z_s[gg][t - 128] = sigmoidf_(gi[gg] + gh[gg]);
                }
                __syncthreads();
                if (t >= 256) {
                    int j = t - 256;
#pragma unroll
                    for (int gg = 0; gg < WG; gg++) {
                        float n = tanhf(gi[gg] + r_s[gg][j] * gh[gg]);
                        float z = z_s[gg][j];
                        float* hp = (float*)&h2[j >> 1][gg];
                        float hold = hp[j & 1];
                        hp[j & 1] = (1.f - z) * n + z * hold;
                    }
                }
                __syncthreads();
            }
            if (t < DM) {
#pragma unroll
                for (int gg = 0; gg < WG; gg++) {
                    g_S4[(p * BATCH * NWIN + g * WG + gg) * DM + t] =
                        ((const float*)&h2[t >> 1][gg])[t & 1];
                }
            }
            __syncthreads();
            ngroups++;
        }
        __threadfence();
        __syncthreads();
        if (t == 0 && ngroups) atomicAdd(&g_scnt[p], ngroups);

        // ---- stats + finalize for batch b = w (first 64 workers) ----
        if (w < BATCH) {
            int b = w;
            int T = SEQ + p;
            if (p >= 1) wait_ctr(&g_ycnt, BATCH * p);   // need y_{p-1}

            float s = 0.f, ss = 0.f;
            if (t < 256) {
                for (int i = t; i < T; i += 256) {
                    float v = (i < SEQ) ? __ldg(&g_x[b * XSTRIDE + i])
                                        : __ldcg(&g_x[b * XSTRIDE + i]);
                    s += v; ss += v * v;
                }
                rs[t] = s; rss[t] = ss;
            }
            __syncthreads();
            for (int o = 128; o > 0; o >>= 1) {
                if (t < o) { rs[t] += rs[t + o]; rss[t] += rss[t + o]; }
                __syncthreads();
            }
            if (t == 0) {
                float mean = rs[0] / (float)T;
                float var  = (rss[0] - (float)T * mean * mean) / (float)(T - 1);
                thresh_sh = mean + 1.48f * sqrtf(fmaxf(var, 0.f));
            }

            wait_ctr(&g_hcnt, BATCH * (p + 1));   // H_p published (all batches)
            wait_ctr(&g_scnt[p], NGROUPS);        // all windows of pred p done

            if (t < NWIN) starts_sh[t] = rand_start(p, b * NWIN + t, span);
            if (t < DM)   H_sh[t] = __ldcg(&g_H4[p * BATCH * DM + b * DM + t]);
            __syncthreads();

            if (t < NWIN) {
                const float* S = g_S4 + (p * BATCH * NWIN + b * NWIN + t) * DM;
                float d = 0.f;
#pragma unroll 4
                for (int h = 0; h < DM; h++) d += H_sh[h] * __ldcg(S + h);
                e_s[t] = d;
            }
            __syncthreads();

            if (t == 0) {
                float mx = -1e30f;
                for (int m = 0; m < NWIN; m++) mx = fmaxf(mx, e_s[m]);
                float se = 0.f;
                for (int m = 0; m < NWIN; m++) { float e = __expf(e_s[m] - mx); e_s[m] = e; se += e; }
                se_sh = se;
            }
            __syncthreads();

            if (t < DM) red[t] = H_sh[t] * __ldg(Wd + t);
            if (t < NWIN) {
                int idx = starts_sh[t] + WLEN;
                float q = (__ldcg(&g_x[b * XSTRIDE + idx]) > thresh_sh) ? 1.f : 0.f;
                qred[t] = q * e_s[t];
            }
            __syncthreads();

            for (int o = 64; o > 0; o >>= 1) {
                if (t < o) red[t] += red[t + o];
                if (o <= 32 && t < o) qred[t] += qred[t + o];
                __syncthreads();
            }

            if (t == 0) {
                float oval = red[0] + __ldg(bd);
                float sc = qred[0] / se_sh;
                float u = sigmoidf_(sc * __ldg(Wc) + __ldg(bc));
                float y = oval + u;
                g_x[b * XSTRIDE + SEQ + p] = y;
                out[b * PRED + p] = y;
                if (out_size >= 2 * BATCH * PRED) out[BATCH * PRED + b * PRED + p] = u;
                __threadfence();
                atomicAdd(&g_ycnt, 1);
            }
            __syncthreads();
        }
    }
}

__global__ void __launch_bounds__(G3, 1) persist_kernel(
    const float* __restrict__ Wi_g, const float* __restrict__ bi_g,
    const float* __restrict__ Wh_g, const float* __restrict__ bh_g,
    const float* __restrict__ Wi_w, const float* __restrict__ bi_w,
    const float* __restrict__ Wh_w, const float* __restrict__ bh_w,
    const float* __restrict__ Wd,   const float* __restrict__ bd,
    const float* __restrict__ Wc,   const float* __restrict__ bc,
    float* __restrict__ out, int out_size)
{
    int cta = blockIdx.x;
    if (cta < BATCH) {
        global_path(cta, Wi_g, bi_g, Wh_g, bh_g);
    } else {
        worker_path(cta - BATCH, Wi_w, bi_w, Wh_w, bh_w, Wd, bd, Wc, bc, out, out_size);
    }
}

// ---------------- launcher (default stream only) ----------------
extern "C" void kernel_launch(void* const* d_in, const int* in_sizes, int n_in,
                              void* d_out, int out_size) {
    const float* batch_x = (const float*)d_in[0];
    const float* Wi_g = (const float*)d_in[4];
    const float* Wh_g = (const float*)d_in[5];
    const float* bi_g = (const float*)d_in[6];
    const float* bh_g = (const float*)d_in[7];
    const float* Wi_w = (const float*)d_in[8];
    const float* Wh_w = (const float*)d_in[9];
    const float* bi_w = (const float*)d_in[10];
    const float* bh_w = (const float*)d_in[11];
    const float* Wd   = (const float*)d_in[12];
    const float* bd   = (const float*)d_in[13];
    const float* Wc   = (const float*)d_in[16];
    const float* bc   = (const float*)d_in[17];
    float* out = (float*)d_out;

    copy_x_kernel<<<(BATCH * SEQ + 255) / 256, 256>>>(batch_x);
    persist_kernel<<<NCTA, G3>>>(Wi_g, bi_g, Wh_g, bh_g,
                                 Wi_w, bi_w, Wh_w, bh_w,
                                 Wd, bd, Wc, bc, out, out_size);
}